// round 6
// baseline (speedup 1.0000x reference)
#include <cuda_runtime.h>
#include <math.h>

// Problem constants
#define FH 256
#define FW 256
#define FC 256
#define FB 2
#define N_ROI 1024          // B*N = 2*512
#define OUT_H 7
#define OUT_W 7
#define NBINS 49            // 7*7
#define HALF_C 128          // channels per pooling block
#define PITCH 52            // s_out row pitch (floats), >= NBINS+3, mult of 4

// Scratch: NHWC-transposed feature map. 2*256*256*256 floats = 128 MB.
__device__ float g_xt[(size_t)FB * FH * FW * FC];

// Separately-rounded f32 ops (never FMA-contracted; match XLA HLO semantics)
__device__ __forceinline__ float mrn(float a, float b) { return __fmul_rn(a, b); }
__device__ __forceinline__ float arn(float a, float b) { return __fadd_rn(a, b); }

// ---------------------------------------------------------------------------
// Kernel 1: (B, C, H, W) -> (B, H*W, C) transpose, float4 + XOR swizzle.
// (unchanged from R5 — proven 5.2 TB/s)
// ---------------------------------------------------------------------------
__global__ void __launch_bounds__(256) transpose_kernel(const float* __restrict__ x) {
    __shared__ float4 tile4[32][32];
    const int b  = blockIdx.z;
    const int p0 = blockIdx.x * 128;  // pixel tile (H*W dim)
    const int c0 = blockIdx.y * 32;   // channel tile
    const int tx = threadIdx.x;       // 0..31
    const int ty = threadIdx.y;       // 0..7

    const float* src = x    + (size_t)b * FC * FH * FW;
    float*       dst = g_xt + (size_t)b * FH * FW * FC;

#pragma unroll
    for (int j = 0; j < 4; ++j) {
        const int c_local = ty + 8 * j;
        const float4 v = *reinterpret_cast<const float4*>(
            src + (size_t)(c0 + c_local) * (FH * FW) + p0 + 4 * tx);
        tile4[c_local][tx ^ c_local] = v;
    }
    __syncthreads();

#pragma unroll
    for (int j = 0; j < 4; ++j) {
        const int p4 = ty + 8 * j;                 // 0..31
        const float4 v = tile4[tx][p4 ^ tx];
        float* d = dst + (size_t)(p0 + 4 * p4) * FC + c0 + tx;
        d[0 * FC] = v.x;
        d[1 * FC] = v.y;
        d[2 * FC] = v.z;
        d[3 * FC] = v.w;
    }
}

// ---------------------------------------------------------------------------
// Kernel 2: rotated ROI pool, float4 gather.
// Grid: (1024 rois, 2 channel-halves). Block: 128 threads =
//   32 channel-quads (c4) x 4 bin-slices (13/13/13/10 bins).
// Per (bin, corner): warp issues one LDG.128 covering 512B of the pixel line.
// Results scattered to smem with row-rotation swizzle (pitch 52,
// col = (bin + c4) % 52) -> conflict-free stores AND conflict-free linear
// flush reads. Geometry identical to R3/R5 (bit-exact).
// ---------------------------------------------------------------------------
__global__ void __launch_bounds__(128) rroi_pool_kernel(
    const float* __restrict__ boxes, float* __restrict__ out)
{
    __shared__ int   s_addr[NBINS][4];   // pixel-line offset in float4 units
    __shared__ float s_w[NBINS][4];      // weight, zeroed if corner invalid
    __shared__ float s_out[HALF_C * PITCH];

    const int roi   = blockIdx.x;
    const int half  = blockIdx.y;
    const int tid   = threadIdx.x;
    const int cbase = half * HALF_C;

    if (tid < NBINS) {
        const float* bx = boxes + (size_t)roi * 5;
        const int b = roi >> 9;                 // N = 512 per batch

        const float cx  = mrn(bx[0], 0.25f);
        const float cy  = mrn(bx[1], 0.25f);
        const float w   = mrn(bx[2], 0.25f);
        const float h   = mrn(bx[3], 0.25f);
        const float ang = mrn(bx[4], (float)(M_PI / 180.0));

        const float ca = cosf(ang);
        const float sa = sinf(ang);
        const float Sx = __fdiv_rn(w, (float)OUT_W);
        const float Sy = __fdiv_rn(h, (float)OUT_H);

        const float dx = -OUT_W / 2.0f;     // -3.5, exact
        const float dy = -OUT_H / 2.0f;     // -3.5, exact

        const float M00 = mrn(ca, Sx);
        const float M01 = mrn(sa, Sy);
        const float M02 = arn(arn(mrn(M00, dx), mrn(M01, dy)), cx);
        const float M10 = mrn(-sa, Sx);
        const float M11 = mrn(ca, Sy);
        const float M12 = arn(arn(mrn(M10, dx), mrn(M11, dy)), cy);

        const int ph = tid / OUT_W;
        const int pw = tid % OUT_W;
        const float pwf = (float)pw;
        const float phf = (float)ph;

        float minX =  1e30f, maxX = -1e30f, minY = 1e30f, maxY = -1e30f;
#pragma unroll
        for (int k = 0; k < 4; ++k) {
            const float ox = (float)(k >> 1);   // offs[:,0] added to pw
            const float oy = (float)(k & 1);    // offs[:,1] added to ph
            const float px = pwf + ox;          // exact (small ints)
            const float py = phf + oy;          // exact
            const float X = arn(arn(mrn(M00, px), mrn(M01, py)), M02);
            const float Y = arn(arn(mrn(M10, px), mrn(M11, py)), M12);
            minX = fminf(minX, X); maxX = fmaxf(maxX, X);
            minY = fminf(minY, Y); maxY = fmaxf(maxY, Y);
        }

        // jnp.round == round-half-even == rintf
        const float leftMost   = fmaxf(rintf(minX), 0.0f);
        const float rightMost  = fminf(rintf(maxX), (float)(FW - 1));
        const float topMost    = fmaxf(rintf(minY), 0.0f);
        const float bottomMost = fminf(rintf(maxY), (float)(FH - 1));

        const float bcx = mrn(arn(leftMost, rightMost), 0.5f);
        const float bcy = mrn(arn(topMost, bottomMost), 0.5f);
        const int bl = (int)floorf(bcx);
        const int br = (int)ceilf(bcx);
        const int bt = (int)floorf(bcy);
        const int bb = (int)ceilf(bcy);
        const float rx = bcx - floorf(bcx);   // exactly 0.0 or 0.5
        const float ry = bcy - floorf(bcy);   // exactly 0.0 or 0.5

        // corner order matches reference accumulation: lt, rt, rb, lb
        const int ys[4] = { bt, bt, bb, bb };
        const int xs[4] = { bl, br, br, bl };
        const float ws[4] = { (1.0f - rx) * (1.0f - ry),
                              rx * (1.0f - ry),
                              rx * ry,
                              (1.0f - rx) * ry };          // all exact (pow2)
        const int pix_base = b * FH * FW;
#pragma unroll
        for (int k = 0; k < 4; ++k) {
            const int y = ys[k], x = xs[k];
            const bool valid = (y >= 0) && (y < FH) && (x >= 0) && (x < FW);
            const int yc = min(max(y, 0), FH - 1);
            const int xc = min(max(x, 0), FW - 1);
            // float4-line offset of this pixel (FC/4 quads per pixel)
            s_addr[tid][k] = (pix_base + yc * FW + xc) * (FC / 4);
            s_w[tid][k]    = valid ? ws[k] : 0.0f;           // mask via weight
        }
    }
    __syncthreads();

    // Phase 2: float4 gather + blend.
    const float4* __restrict__ xt4 = reinterpret_cast<const float4*>(g_xt);
    const int c4    = tid & 31;            // channel-quad within half
    const int slice = tid >> 5;            // 0..3
    const int cgo   = (cbase >> 2) + c4;   // quad offset within pixel line
    const int b0    = slice * 13;
    const int b1    = (b0 + 13 < NBINS) ? (b0 + 13) : NBINS;

#pragma unroll 2
    for (int bin = b0; bin < b1; ++bin) {
        const float4 x0 = __ldg(&xt4[s_addr[bin][0] + cgo]);
        const float4 x1 = __ldg(&xt4[s_addr[bin][1] + cgo]);
        const float4 x2 = __ldg(&xt4[s_addr[bin][2] + cgo]);
        const float4 x3 = __ldg(&xt4[s_addr[bin][3] + cgo]);
        const float w0 = s_w[bin][0];
        const float w1 = s_w[bin][1];
        const float w2 = s_w[bin][2];
        const float w3 = s_w[bin][3];

        float v[4];
        v[0] = fmaxf(arn(arn(arn(arn(0.0f, mrn(x0.x, w0)), mrn(x1.x, w1)), mrn(x2.x, w2)), mrn(x3.x, w3)), 0.0f);
        v[1] = fmaxf(arn(arn(arn(arn(0.0f, mrn(x0.y, w0)), mrn(x1.y, w1)), mrn(x2.y, w2)), mrn(x3.y, w3)), 0.0f);
        v[2] = fmaxf(arn(arn(arn(arn(0.0f, mrn(x0.z, w0)), mrn(x1.z, w1)), mrn(x2.z, w2)), mrn(x3.z, w3)), 0.0f);
        v[3] = fmaxf(arn(arn(arn(arn(0.0f, mrn(x0.w, w0)), mrn(x1.w, w1)), mrn(x2.w, w2)), mrn(x3.w, w3)), 0.0f);

        // Rotated scatter: row ch=4*c4+q, col=(bin+c4)%PITCH.
        // Store bank = 17*c4 + 20*q + bin (mod 32): distinct across lanes.
        int col = bin + c4; if (col >= PITCH) col -= PITCH;
#pragma unroll
        for (int q = 0; q < 4; ++q)
            s_out[(4 * c4 + q) * PITCH + col] = v[q];
    }
    __syncthreads();

    // Phase 3: coalesced flush; smem reads are consecutive-address per lane
    // (rotation depends only on the channel row) -> conflict-free.
    float* dst = out + (size_t)roi * (FC * NBINS) + (size_t)cbase * NBINS;
#pragma unroll 4
    for (int i = tid; i < HALF_C * NBINS; i += 128) {
        const int ch  = i / NBINS;
        const int bin = i - ch * NBINS;
        int col = bin + (ch >> 2); if (col >= PITCH) col -= PITCH;
        dst[i] = s_out[ch * PITCH + col];
    }
}

extern "C" void kernel_launch(void* const* d_in, const int* in_sizes, int n_in,
                              void* d_out, int out_size) {
    const float* x     = (const float*)d_in[0];   // (2,256,256,256) f32
    const float* boxes = (const float*)d_in[1];   // (2,512,5) f32
    float* out = (float*)d_out;                   // (1024,256,7,7) f32

    // 1) NCHW -> NHWC transpose into scratch (float4 both sides via swizzle)
    transpose_kernel<<<dim3(FH * FW / 128, FC / 32, FB), dim3(32, 8)>>>(x);

    // 2) rotated ROI pool (float4 gather)
    rroi_pool_kernel<<<dim3(N_ROI, 2), HALF_C>>>(boxes, out);
}

// round 8
// speedup vs baseline: 1.0509x; 1.0509x over previous
#include <cuda_runtime.h>
#include <math.h>

// Problem constants
#define FH 256
#define FW 256
#define FC 256
#define FB 2
#define N_ROI 1024          // B*N = 2*512
#define OUT_H 7
#define OUT_W 7
#define NBINS 49            // 7*7
#define HALF_C 128          // channels per pooling block
#define PITCH 52            // s_out row pitch (floats), >= NBINS+3, mult of 4

// Scratch: NHWC-transposed feature map. 2*256*256*256 floats = 128 MB.
__device__ float g_xt[(size_t)FB * FH * FW * FC];

// Separately-rounded f32 ops (never FMA-contracted; match XLA HLO semantics)
__device__ __forceinline__ float mrn(float a, float b) { return __fmul_rn(a, b); }
__device__ __forceinline__ float arn(float a, float b) { return __fadd_rn(a, b); }

// ---------------------------------------------------------------------------
// Kernel 1: (B, C, H, W) -> (B, H*W, C) transpose, float4 + XOR swizzle.
// (unchanged — proven 5.2 TB/s)
// ---------------------------------------------------------------------------
__global__ void __launch_bounds__(256) transpose_kernel(const float* __restrict__ x) {
    __shared__ float4 tile4[32][32];
    const int b  = blockIdx.z;
    const int p0 = blockIdx.x * 128;  // pixel tile (H*W dim)
    const int c0 = blockIdx.y * 32;   // channel tile
    const int tx = threadIdx.x;       // 0..31
    const int ty = threadIdx.y;       // 0..7

    const float* src = x    + (size_t)b * FC * FH * FW;
    float*       dst = g_xt + (size_t)b * FH * FW * FC;

#pragma unroll
    for (int j = 0; j < 4; ++j) {
        const int c_local = ty + 8 * j;
        const float4 v = *reinterpret_cast<const float4*>(
            src + (size_t)(c0 + c_local) * (FH * FW) + p0 + 4 * tx);
        tile4[c_local][tx ^ c_local] = v;
    }
    __syncthreads();

#pragma unroll
    for (int j = 0; j < 4; ++j) {
        const int p4 = ty + 8 * j;                 // 0..31
        const float4 v = tile4[tx][p4 ^ tx];
        float* d = dst + (size_t)(p0 + 4 * p4) * FC + c0 + tx;
        d[0 * FC] = v.x;
        d[1 * FC] = v.y;
        d[2 * FC] = v.z;
        d[3 * FC] = v.w;
    }
}

// ---------------------------------------------------------------------------
// Kernel 2: rotated ROI pool, float4 gather (R6 structure, ALU/MLP fixed).
// Grid: (1024 rois, 2 channel-halves). Block: 128 threads =
//   32 channel-quads (c4) x 4 bin-slices (13/13/13/10 bins).
// unroll 4 -> 16 LDG.128 in flight per thread. Flush is division-free.
// ---------------------------------------------------------------------------
__global__ void __launch_bounds__(128) rroi_pool_kernel(
    const float* __restrict__ boxes, float* __restrict__ out)
{
    __shared__ int   s_addr[NBINS][4];   // pixel-line offset in float4 units
    __shared__ float s_w[NBINS][4];      // weight, zeroed if corner invalid
    __shared__ float s_out[HALF_C * PITCH];

    const int roi   = blockIdx.x;
    const int half  = blockIdx.y;
    const int tid   = threadIdx.x;
    const int cbase = half * HALF_C;

    if (tid < NBINS) {
        const float* bx = boxes + (size_t)roi * 5;
        const int b = roi >> 9;                 // N = 512 per batch

        const float cx  = mrn(bx[0], 0.25f);
        const float cy  = mrn(bx[1], 0.25f);
        const float w   = mrn(bx[2], 0.25f);
        const float h   = mrn(bx[3], 0.25f);
        const float ang = mrn(bx[4], (float)(M_PI / 180.0));

        const float ca = cosf(ang);
        const float sa = sinf(ang);
        const float Sx = __fdiv_rn(w, (float)OUT_W);
        const float Sy = __fdiv_rn(h, (float)OUT_H);

        const float dx = -OUT_W / 2.0f;     // -3.5, exact
        const float dy = -OUT_H / 2.0f;     // -3.5, exact

        const float M00 = mrn(ca, Sx);
        const float M01 = mrn(sa, Sy);
        const float M02 = arn(arn(mrn(M00, dx), mrn(M01, dy)), cx);
        const float M10 = mrn(-sa, Sx);
        const float M11 = mrn(ca, Sy);
        const float M12 = arn(arn(mrn(M10, dx), mrn(M11, dy)), cy);

        const int ph = tid / OUT_W;
        const int pw = tid % OUT_W;
        const float pwf = (float)pw;
        const float phf = (float)ph;

        float minX =  1e30f, maxX = -1e30f, minY = 1e30f, maxY = -1e30f;
#pragma unroll
        for (int k = 0; k < 4; ++k) {
            const float ox = (float)(k >> 1);   // offs[:,0] added to pw
            const float oy = (float)(k & 1);    // offs[:,1] added to ph
            const float px = pwf + ox;          // exact (small ints)
            const float py = phf + oy;          // exact
            const float X = arn(arn(mrn(M00, px), mrn(M01, py)), M02);
            const float Y = arn(arn(mrn(M10, px), mrn(M11, py)), M12);
            minX = fminf(minX, X); maxX = fmaxf(maxX, X);
            minY = fminf(minY, Y); maxY = fmaxf(maxY, Y);
        }

        // jnp.round == round-half-even == rintf
        const float leftMost   = fmaxf(rintf(minX), 0.0f);
        const float rightMost  = fminf(rintf(maxX), (float)(FW - 1));
        const float topMost    = fmaxf(rintf(minY), 0.0f);
        const float bottomMost = fminf(rintf(maxY), (float)(FH - 1));

        const float bcx = mrn(arn(leftMost, rightMost), 0.5f);
        const float bcy = mrn(arn(topMost, bottomMost), 0.5f);
        const int bl = (int)floorf(bcx);
        const int br = (int)ceilf(bcx);
        const int bt = (int)floorf(bcy);
        const int bb = (int)ceilf(bcy);
        const float rx = bcx - floorf(bcx);   // exactly 0.0 or 0.5
        const float ry = bcy - floorf(bcy);   // exactly 0.0 or 0.5

        // corner order matches reference accumulation: lt, rt, rb, lb
        const int ys[4] = { bt, bt, bb, bb };
        const int xs[4] = { bl, br, br, bl };
        const float ws[4] = { (1.0f - rx) * (1.0f - ry),
                              rx * (1.0f - ry),
                              rx * ry,
                              (1.0f - rx) * ry };          // all exact (pow2)
        const int pix_base = b * FH * FW;
#pragma unroll
        for (int k = 0; k < 4; ++k) {
            const int y = ys[k], x = xs[k];
            const bool valid = (y >= 0) && (y < FH) && (x >= 0) && (x < FW);
            const int yc = min(max(y, 0), FH - 1);
            const int xc = min(max(x, 0), FW - 1);
            // float4-line offset of this pixel (FC/4 quads per pixel)
            s_addr[tid][k] = (pix_base + yc * FW + xc) * (FC / 4);
            s_w[tid][k]    = valid ? ws[k] : 0.0f;           // mask via weight
        }
    }
    __syncthreads();

    // Phase 2: float4 gather + blend. unroll 4 -> 16 loads in flight.
    const float4* __restrict__ xt4 = reinterpret_cast<const float4*>(g_xt);
    const int c4    = tid & 31;            // channel-quad within half
    const int slice = tid >> 5;            // 0..3
    const int cgo   = (cbase >> 2) + c4;   // quad offset within pixel line
    const int b0    = slice * 13;
    const int b1    = (b0 + 13 < NBINS) ? (b0 + 13) : NBINS;
    float* const srow = s_out + 4 * c4 * PITCH;   // hoisted scatter base

#pragma unroll 4
    for (int bin = b0; bin < b1; ++bin) {
        const float4 x0 = __ldg(&xt4[s_addr[bin][0] + cgo]);
        const float4 x1 = __ldg(&xt4[s_addr[bin][1] + cgo]);
        const float4 x2 = __ldg(&xt4[s_addr[bin][2] + cgo]);
        const float4 x3 = __ldg(&xt4[s_addr[bin][3] + cgo]);
        const float w0 = s_w[bin][0];
        const float w1 = s_w[bin][1];
        const float w2 = s_w[bin][2];
        const float w3 = s_w[bin][3];

        float v[4];
        v[0] = fmaxf(arn(arn(arn(arn(0.0f, mrn(x0.x, w0)), mrn(x1.x, w1)), mrn(x2.x, w2)), mrn(x3.x, w3)), 0.0f);
        v[1] = fmaxf(arn(arn(arn(arn(0.0f, mrn(x0.y, w0)), mrn(x1.y, w1)), mrn(x2.y, w2)), mrn(x3.y, w3)), 0.0f);
        v[2] = fmaxf(arn(arn(arn(arn(0.0f, mrn(x0.z, w0)), mrn(x1.z, w1)), mrn(x2.z, w2)), mrn(x3.z, w3)), 0.0f);
        v[3] = fmaxf(arn(arn(arn(arn(0.0f, mrn(x0.w, w0)), mrn(x1.w, w1)), mrn(x2.w, w2)), mrn(x3.w, w3)), 0.0f);

        // Rotated scatter: row ch=4*c4+q, col=(bin+c4)%PITCH -> conflict-free.
        int col = bin + c4; if (col >= PITCH) col -= PITCH;
#pragma unroll
        for (int q = 0; q < 4; ++q)
            srow[q * PITCH + col] = v[q];
    }
    __syncthreads();

    // Phase 3: coalesced flush, division-free (ch,bin updated incrementally).
    float* dst = out + (size_t)roi * (FC * NBINS) + (size_t)cbase * NBINS;
    {
        int ch  = tid / NBINS;              // one division total (tid<128 -> 0..2)
        int bin = tid - ch * NBINS;
        int rowbase = ch * PITCH;
#pragma unroll 4
        for (int i = tid; i < HALF_C * NBINS; i += 128) {
            int col = bin + (ch >> 2); if (col >= PITCH) col -= PITCH;
            dst[i] = s_out[rowbase + col];
            // advance by 128 = 2*49 + 30
            bin += 30; ch += 2; rowbase += 2 * PITCH;
            if (bin >= NBINS) { bin -= NBINS; ++ch; rowbase += PITCH; }
        }
    }
}

extern "C" void kernel_launch(void* const* d_in, const int* in_sizes, int n_in,
                              void* d_out, int out_size) {
    const float* x     = (const float*)d_in[0];   // (2,256,256,256) f32
    const float* boxes = (const float*)d_in[1];   // (2,512,5) f32
    float* out = (float*)d_out;                   // (1024,256,7,7) f32

    // 1) NCHW -> NHWC transpose into scratch (float4 both sides via swizzle)
    transpose_kernel<<<dim3(FH * FW / 128, FC / 32, FB), dim3(32, 8)>>>(x);

    // 2) rotated ROI pool (float4 gather)
    rroi_pool_kernel<<<dim3(N_ROI, 2), HALF_C>>>(boxes, out);
}

// round 9
// speedup vs baseline: 1.0521x; 1.0012x over previous
#include <cuda_runtime.h>
#include <math.h>

// Problem constants
#define FH 256
#define FW 256
#define FC 256
#define FB 2
#define N_ROI 1024          // B*N = 2*512
#define OUT_H 7
#define OUT_W 7
#define NBINS 49            // 7*7
#define HALF_C 128          // channels per pooling block
#define PITCH 52            // s_out row pitch (floats), >= NBINS+3, mult of 4

// Scratch: NHWC-transposed feature map. 2*256*256*256 floats = 128 MB.
__device__ float g_xt[(size_t)FB * FH * FW * FC];

// Separately-rounded f32 ops (never FMA-contracted; match XLA HLO semantics)
__device__ __forceinline__ float mrn(float a, float b) { return __fmul_rn(a, b); }
__device__ __forceinline__ float arn(float a, float b) { return __fadd_rn(a, b); }

// ---------------------------------------------------------------------------
// Kernel 1: (B, C, H, W) -> (B, H*W, C) transpose, float4 + XOR swizzle.
// (unchanged — proven 5.2 TB/s)
// ---------------------------------------------------------------------------
__global__ void __launch_bounds__(256) transpose_kernel(const float* __restrict__ x) {
    __shared__ float4 tile4[32][32];
    const int b  = blockIdx.z;
    const int p0 = blockIdx.x * 128;  // pixel tile (H*W dim)
    const int c0 = blockIdx.y * 32;   // channel tile
    const int tx = threadIdx.x;       // 0..31
    const int ty = threadIdx.y;       // 0..7

    const float* src = x    + (size_t)b * FC * FH * FW;
    float*       dst = g_xt + (size_t)b * FH * FW * FC;

#pragma unroll
    for (int j = 0; j < 4; ++j) {
        const int c_local = ty + 8 * j;
        const float4 v = *reinterpret_cast<const float4*>(
            src + (size_t)(c0 + c_local) * (FH * FW) + p0 + 4 * tx);
        tile4[c_local][tx ^ c_local] = v;
    }
    __syncthreads();

#pragma unroll
    for (int j = 0; j < 4; ++j) {
        const int p4 = ty + 8 * j;                 // 0..31
        const float4 v = tile4[tx][p4 ^ tx];
        float* d = dst + (size_t)(p0 + 4 * p4) * FC + c0 + tx;
        d[0 * FC] = v.x;
        d[1 * FC] = v.y;
        d[2 * FC] = v.z;
        d[3 * FC] = v.w;
    }
}

// ---------------------------------------------------------------------------
// Kernel 2: rotated ROI pool, float4 gather (R6 structure, ALU/MLP fixed).
// Grid: (1024 rois, 2 channel-halves). Block: 128 threads =
//   32 channel-quads (c4) x 4 bin-slices (13/13/13/10 bins).
// unroll 4 -> 16 LDG.128 in flight per thread. Flush is division-free.
// ---------------------------------------------------------------------------
__global__ void __launch_bounds__(128) rroi_pool_kernel(
    const float* __restrict__ boxes, float* __restrict__ out)
{
    __shared__ int   s_addr[NBINS][4];   // pixel-line offset in float4 units
    __shared__ float s_w[NBINS][4];      // weight, zeroed if corner invalid
    __shared__ float s_out[HALF_C * PITCH];

    const int roi   = blockIdx.x;
    const int half  = blockIdx.y;
    const int tid   = threadIdx.x;
    const int cbase = half * HALF_C;

    if (tid < NBINS) {
        const float* bx = boxes + (size_t)roi * 5;
        const int b = roi >> 9;                 // N = 512 per batch

        const float cx  = mrn(bx[0], 0.25f);
        const float cy  = mrn(bx[1], 0.25f);
        const float w   = mrn(bx[2], 0.25f);
        const float h   = mrn(bx[3], 0.25f);
        const float ang = mrn(bx[4], (float)(M_PI / 180.0));

        const float ca = cosf(ang);
        const float sa = sinf(ang);
        const float Sx = __fdiv_rn(w, (float)OUT_W);
        const float Sy = __fdiv_rn(h, (float)OUT_H);

        const float dx = -OUT_W / 2.0f;     // -3.5, exact
        const float dy = -OUT_H / 2.0f;     // -3.5, exact

        const float M00 = mrn(ca, Sx);
        const float M01 = mrn(sa, Sy);
        const float M02 = arn(arn(mrn(M00, dx), mrn(M01, dy)), cx);
        const float M10 = mrn(-sa, Sx);
        const float M11 = mrn(ca, Sy);
        const float M12 = arn(arn(mrn(M10, dx), mrn(M11, dy)), cy);

        const int ph = tid / OUT_W;
        const int pw = tid % OUT_W;
        const float pwf = (float)pw;
        const float phf = (float)ph;

        float minX =  1e30f, maxX = -1e30f, minY = 1e30f, maxY = -1e30f;
#pragma unroll
        for (int k = 0; k < 4; ++k) {
            const float ox = (float)(k >> 1);   // offs[:,0] added to pw
            const float oy = (float)(k & 1);    // offs[:,1] added to ph
            const float px = pwf + ox;          // exact (small ints)
            const float py = phf + oy;          // exact
            const float X = arn(arn(mrn(M00, px), mrn(M01, py)), M02);
            const float Y = arn(arn(mrn(M10, px), mrn(M11, py)), M12);
            minX = fminf(minX, X); maxX = fmaxf(maxX, X);
            minY = fminf(minY, Y); maxY = fmaxf(maxY, Y);
        }

        // jnp.round == round-half-even == rintf
        const float leftMost   = fmaxf(rintf(minX), 0.0f);
        const float rightMost  = fminf(rintf(maxX), (float)(FW - 1));
        const float topMost    = fmaxf(rintf(minY), 0.0f);
        const float bottomMost = fminf(rintf(maxY), (float)(FH - 1));

        const float bcx = mrn(arn(leftMost, rightMost), 0.5f);
        const float bcy = mrn(arn(topMost, bottomMost), 0.5f);
        const int bl = (int)floorf(bcx);
        const int br = (int)ceilf(bcx);
        const int bt = (int)floorf(bcy);
        const int bb = (int)ceilf(bcy);
        const float rx = bcx - floorf(bcx);   // exactly 0.0 or 0.5
        const float ry = bcy - floorf(bcy);   // exactly 0.0 or 0.5

        // corner order matches reference accumulation: lt, rt, rb, lb
        const int ys[4] = { bt, bt, bb, bb };
        const int xs[4] = { bl, br, br, bl };
        const float ws[4] = { (1.0f - rx) * (1.0f - ry),
                              rx * (1.0f - ry),
                              rx * ry,
                              (1.0f - rx) * ry };          // all exact (pow2)
        const int pix_base = b * FH * FW;
#pragma unroll
        for (int k = 0; k < 4; ++k) {
            const int y = ys[k], x = xs[k];
            const bool valid = (y >= 0) && (y < FH) && (x >= 0) && (x < FW);
            const int yc = min(max(y, 0), FH - 1);
            const int xc = min(max(x, 0), FW - 1);
            // float4-line offset of this pixel (FC/4 quads per pixel)
            s_addr[tid][k] = (pix_base + yc * FW + xc) * (FC / 4);
            s_w[tid][k]    = valid ? ws[k] : 0.0f;           // mask via weight
        }
    }
    __syncthreads();

    // Phase 2: float4 gather + blend. unroll 4 -> 16 loads in flight.
    const float4* __restrict__ xt4 = reinterpret_cast<const float4*>(g_xt);
    const int c4    = tid & 31;            // channel-quad within half
    const int slice = tid >> 5;            // 0..3
    const int cgo   = (cbase >> 2) + c4;   // quad offset within pixel line
    const int b0    = slice * 13;
    const int b1    = (b0 + 13 < NBINS) ? (b0 + 13) : NBINS;
    float* const srow = s_out + 4 * c4 * PITCH;   // hoisted scatter base

#pragma unroll 4
    for (int bin = b0; bin < b1; ++bin) {
        const float4 x0 = __ldg(&xt4[s_addr[bin][0] + cgo]);
        const float4 x1 = __ldg(&xt4[s_addr[bin][1] + cgo]);
        const float4 x2 = __ldg(&xt4[s_addr[bin][2] + cgo]);
        const float4 x3 = __ldg(&xt4[s_addr[bin][3] + cgo]);
        const float w0 = s_w[bin][0];
        const float w1 = s_w[bin][1];
        const float w2 = s_w[bin][2];
        const float w3 = s_w[bin][3];

        float v[4];
        v[0] = fmaxf(arn(arn(arn(arn(0.0f, mrn(x0.x, w0)), mrn(x1.x, w1)), mrn(x2.x, w2)), mrn(x3.x, w3)), 0.0f);
        v[1] = fmaxf(arn(arn(arn(arn(0.0f, mrn(x0.y, w0)), mrn(x1.y, w1)), mrn(x2.y, w2)), mrn(x3.y, w3)), 0.0f);
        v[2] = fmaxf(arn(arn(arn(arn(0.0f, mrn(x0.z, w0)), mrn(x1.z, w1)), mrn(x2.z, w2)), mrn(x3.z, w3)), 0.0f);
        v[3] = fmaxf(arn(arn(arn(arn(0.0f, mrn(x0.w, w0)), mrn(x1.w, w1)), mrn(x2.w, w2)), mrn(x3.w, w3)), 0.0f);

        // Rotated scatter: row ch=4*c4+q, col=(bin+c4)%PITCH -> conflict-free.
        int col = bin + c4; if (col >= PITCH) col -= PITCH;
#pragma unroll
        for (int q = 0; q < 4; ++q)
            srow[q * PITCH + col] = v[q];
    }
    __syncthreads();

    // Phase 3: coalesced flush, division-free (ch,bin updated incrementally).
    float* dst = out + (size_t)roi * (FC * NBINS) + (size_t)cbase * NBINS;
    {
        int ch  = tid / NBINS;              // one division total (tid<128 -> 0..2)
        int bin = tid - ch * NBINS;
        int rowbase = ch * PITCH;
#pragma unroll 4
        for (int i = tid; i < HALF_C * NBINS; i += 128) {
            int col = bin + (ch >> 2); if (col >= PITCH) col -= PITCH;
            dst[i] = s_out[rowbase + col];
            // advance by 128 = 2*49 + 30
            bin += 30; ch += 2; rowbase += 2 * PITCH;
            if (bin >= NBINS) { bin -= NBINS; ++ch; rowbase += PITCH; }
        }
    }
}

extern "C" void kernel_launch(void* const* d_in, const int* in_sizes, int n_in,
                              void* d_out, int out_size) {
    const float* x     = (const float*)d_in[0];   // (2,256,256,256) f32
    const float* boxes = (const float*)d_in[1];   // (2,512,5) f32
    float* out = (float*)d_out;                   // (1024,256,7,7) f32

    // 1) NCHW -> NHWC transpose into scratch (float4 both sides via swizzle)
    transpose_kernel<<<dim3(FH * FW / 128, FC / 32, FB), dim3(32, 8)>>>(x);

    // 2) rotated ROI pool (float4 gather)
    rroi_pool_kernel<<<dim3(N_ROI, 2), HALF_C>>>(boxes, out);
}